// round 3
// baseline (speedup 1.0000x reference)
#include <cuda_runtime.h>
#include <cuda_bf16.h>

// Problem constants (from reference)
#define BB 8
#define CC 32
#define TT 12
#define NNODE 5000
#define EDGES 80000
#define FF (BB*TT*CC)   // 3072 features per node
#define F4 (FF/4)       // 768 float4 per node
#define BT (BB*TT)      // 96

// ---------------------------------------------------------------------------
// Scratch (static __device__ arrays — no allocations allowed)
// ---------------------------------------------------------------------------
__device__ float4 g_y  [(size_t)NNODE * F4];   // y = norm_src * (x W), node-major [n][b][t][c]
__device__ float4 g_agg[(size_t)NNODE * F4];   // aggregated, node-major
__device__ int    g_deg_in [NNODE];
__device__ int    g_deg_out[NNODE];
__device__ int    g_ptr    [NNODE + 1];        // CSR row ptr by dst
__device__ int    g_cursor [NNODE];
__device__ int    g_csr_src[EDGES];            // src node per edge, bucketed by dst
__device__ float  g_norm_src[NNODE];
__device__ float  g_norm_dst[NNODE];

// ---------------------------------------------------------------------------
// K0: zero counters (must run every launch — graph replays re-execute all work)
// ---------------------------------------------------------------------------
__global__ void k_zero() {
    int n = blockIdx.x * blockDim.x + threadIdx.x;
    if (n < NNODE) {
        g_deg_in[n] = 0;
        g_deg_out[n] = 0;
        g_cursor[n] = 0;
    }
}

// ---------------------------------------------------------------------------
// K1: degree histograms
// ---------------------------------------------------------------------------
__global__ void k_deg(const int* __restrict__ src, const int* __restrict__ dst) {
    int e = blockIdx.x * blockDim.x + threadIdx.x;
    if (e < EDGES) {
        atomicAdd(&g_deg_out[src[e]], 1);
        atomicAdd(&g_deg_in [dst[e]], 1);
    }
}

// ---------------------------------------------------------------------------
// K2: norms = max(deg,1)^{-1/2}
// ---------------------------------------------------------------------------
__global__ void k_norm() {
    int n = blockIdx.x * blockDim.x + threadIdx.x;
    if (n < NNODE) {
        g_norm_src[n] = rsqrtf((float)max(g_deg_out[n], 1));
        g_norm_dst[n] = rsqrtf((float)max(g_deg_in[n], 1));
    }
}

// ---------------------------------------------------------------------------
// K3: exclusive prefix sum of deg_in -> g_ptr (single block, Hillis-Steele)
// ---------------------------------------------------------------------------
__global__ void k_scan() {
    __shared__ int s[1024];
    __shared__ int carry;
    int tid = threadIdx.x;
    if (tid == 0) { g_ptr[0] = 0; carry = 0; }
    __syncthreads();
    for (int base = 0; base < NNODE; base += 1024) {
        int i = base + tid;
        int v = (i < NNODE) ? g_deg_in[i] : 0;
        s[tid] = v;
        __syncthreads();
        #pragma unroll
        for (int off = 1; off < 1024; off <<= 1) {
            int t = (tid >= off) ? s[tid - off] : 0;
            __syncthreads();
            s[tid] += t;
            __syncthreads();
        }
        int incl = s[tid];
        if (i < NNODE) g_ptr[i + 1] = carry + incl;
        __syncthreads();
        if (tid == 1023) carry += incl;
        __syncthreads();
    }
}

// ---------------------------------------------------------------------------
// K4: bucket edges by dst
// ---------------------------------------------------------------------------
__global__ void k_scatter(const int* __restrict__ src, const int* __restrict__ dst) {
    int e = blockIdx.x * blockDim.x + threadIdx.x;
    if (e < EDGES) {
        int d = dst[e];
        int pos = g_ptr[d] + atomicAdd(&g_cursor[d], 1);
        g_csr_src[pos] = src[e];
    }
}

// ---------------------------------------------------------------------------
// K5: y[n][bt][c'] = norm_src[n] * sum_c x[b,c,t,n] * W[c][c']
// Block = (32 nodes) x (8 bt-pairs). x loads coalesced over n; y stored
// node-major via float4 (contiguous 128B per thread).
// ---------------------------------------------------------------------------
__global__ void k_y(const float* __restrict__ x, const float* __restrict__ W) {
    __shared__ float Ws[CC * CC];
    int tid = threadIdx.y * 32 + threadIdx.x;
    for (int i = tid; i < CC * CC; i += 256) Ws[i] = W[i];
    __syncthreads();

    int n  = blockIdx.x * 32 + threadIdx.x;
    int bt = blockIdx.y * 8 + threadIdx.y;
    if (n >= NNODE) return;
    int b = bt / TT, t = bt - b * TT;

    // x index: ((b*CC + c)*TT + t)*NNODE + n
    const float* xp = x + ((size_t)b * CC * TT) * NNODE + (size_t)t * NNODE + n;
    float xa[CC];
    #pragma unroll
    for (int c = 0; c < CC; c++) xa[c] = xp[(size_t)c * TT * NNODE];

    float ns = g_norm_src[n];
    float4* yp = g_y + (size_t)n * F4 + bt * (CC / 4);
    #pragma unroll
    for (int c4 = 0; c4 < CC / 4; c4++) {
        float4 acc = make_float4(0.f, 0.f, 0.f, 0.f);
        #pragma unroll
        for (int c = 0; c < CC; c++) {
            float xv = xa[c];
            const float* wr = &Ws[c * CC + c4 * 4];
            acc.x += xv * wr[0];
            acc.y += xv * wr[1];
            acc.z += xv * wr[2];
            acc.w += xv * wr[3];
        }
        acc.x *= ns; acc.y *= ns; acc.z *= ns; acc.w *= ns;
        yp[c4] = acc;
    }
}

// ---------------------------------------------------------------------------
// K6: agg[d] = norm_dst[d] * sum_{e in CSR[d]} y[src[e]]
// One block per dst node, 256 threads, 3 float4 (12 floats) per thread.
// Gather reads are contiguous 12KB per edge, fully coalesced, mostly L2-hit.
// No atomics.
// ---------------------------------------------------------------------------
__global__ void k_agg() {
    int d = blockIdx.x;
    int tid = threadIdx.x;
    int beg = g_ptr[d], end = g_ptr[d + 1];

    float4 a0 = make_float4(0.f, 0.f, 0.f, 0.f);
    float4 a1 = a0, a2 = a0;

    __shared__ int ss[256];
    for (int base = beg; base < end; base += 256) {
        int m = min(256, end - base);
        if (tid < m) ss[tid] = g_csr_src[base + tid];
        __syncthreads();
        #pragma unroll 4
        for (int i = 0; i < m; i++) {
            const float4* ys = g_y + (size_t)ss[i] * F4;
            float4 v0 = ys[tid];
            float4 v1 = ys[tid + 256];
            float4 v2 = ys[tid + 512];
            a0.x += v0.x; a0.y += v0.y; a0.z += v0.z; a0.w += v0.w;
            a1.x += v1.x; a1.y += v1.y; a1.z += v1.z; a1.w += v1.w;
            a2.x += v2.x; a2.y += v2.y; a2.z += v2.z; a2.w += v2.w;
        }
        __syncthreads();
    }

    float nd = g_norm_dst[d];
    a0.x *= nd; a0.y *= nd; a0.z *= nd; a0.w *= nd;
    a1.x *= nd; a1.y *= nd; a1.z *= nd; a1.w *= nd;
    a2.x *= nd; a2.y *= nd; a2.z *= nd; a2.w *= nd;

    float4* ap = g_agg + (size_t)d * F4;
    ap[tid]       = a0;
    ap[tid + 256] = a1;
    ap[tid + 512] = a2;
}

// ---------------------------------------------------------------------------
// K7: out[b,c,t,n] = relu(x[b,c,t,n] + bias[c] + agg[n][b][t][c])
// smem 32x32 tile transpose: agg read coalesced over c, out/x coalesced over n.
// ---------------------------------------------------------------------------
__global__ void k_out(const float* __restrict__ x, const float* __restrict__ bias,
                      float* __restrict__ out) {
    __shared__ float s[32][33];
    int bt = blockIdx.y;
    int b = bt / TT, t = bt - b * TT;
    int n0 = blockIdx.x * 32;
    const float* aggf = (const float*)g_agg;

    #pragma unroll
    for (int k = 0; k < 4; k++) {
        int nl = threadIdx.y + k * 8;
        int n = n0 + nl;
        if (n < NNODE)
            s[nl][threadIdx.x] = aggf[(size_t)n * FF + bt * CC + threadIdx.x];
    }
    __syncthreads();

    int n = n0 + threadIdx.x;
    if (n < NNODE) {
        #pragma unroll
        for (int k = 0; k < 4; k++) {
            int c = threadIdx.y + k * 8;
            size_t idx = (((size_t)b * CC + c) * TT + t) * NNODE + n;
            float v = x[idx] + bias[c] + s[threadIdx.x][c];
            out[idx] = fmaxf(v, 0.0f);
        }
    }
}

// ---------------------------------------------------------------------------
// Launch
// ---------------------------------------------------------------------------
extern "C" void kernel_launch(void* const* d_in, const int* in_sizes, int n_in,
                              void* d_out, int out_size) {
    const float* x    = (const float*)d_in[0];  // [B, C, T, N]
    const float* W    = (const float*)d_in[1];  // [C, C]
    const float* bias = (const float*)d_in[2];  // [C]
    const int*   src  = (const int*)d_in[3];    // [E]
    const int*   dst  = (const int*)d_in[4];    // [E]
    float*       out  = (float*)d_out;          // [B, C, T, N]

    k_zero<<<(NNODE + 255) / 256, 256>>>();
    k_deg<<<(EDGES + 255) / 256, 256>>>(src, dst);
    k_norm<<<(NNODE + 255) / 256, 256>>>();
    k_scan<<<1, 1024>>>();
    k_scatter<<<(EDGES + 255) / 256, 256>>>(src, dst);

    dim3 by((NNODE + 31) / 32, BT / 8);
    k_y<<<by, dim3(32, 8)>>>(x, W);

    k_agg<<<NNODE, 256>>>();

    k_out<<<dim3((NNODE + 31) / 32, BT), dim3(32, 8)>>>(x, bias, out);
}